// round 1
// baseline (speedup 1.0000x reference)
#include <cuda_runtime.h>
#include <math.h>

// Problem constants (from reference setup_inputs)
#define N_TOK   8192
#define DIM     1024
#define VOCAB   50257
#define IGNORE  (-100)

// Tiling
#define NSLICES 8
#define SLICE_W 6283      // ceil(50257 / 8)
#define BM      128
#define BN      128
#define BK      16

// Allocation-free scratch (device globals are allowed)
__device__ float g_pm[NSLICES * N_TOK];   // per-(slice,row) running max
__device__ float g_ps[NSLICES * N_TOK];   // per-(slice,row) sum of exp(x - max)
__device__ float g_nll[N_TOK];

// ---------------------------------------------------------------------------
// Target dtype sniffing: reference requests int64 but default JAX config may
// silently produce int32. For little-endian int64 targets in [-100, VOCAB),
// every odd 32-bit word is 0 (or -1 for negatives). For random int32 targets
// the odd words are random vocab ids — the all-{0,-1} pattern is impossible.
// ---------------------------------------------------------------------------
__device__ __forceinline__ bool targets_are_i64(const int* t32) {
#pragma unroll
    for (int j = 1; j < 64; j += 2) {
        int w = t32[j];
        if (w != 0 && w != -1) return false;
    }
    return true;
}
__device__ __forceinline__ long long get_target(const void* tp, int row, bool is64) {
    if (is64) return ((const long long*)tp)[row];
    return (long long)((const int*)tp)[row];
}

// ---------------------------------------------------------------------------
// Kernel 1: tiled fp32 GEMM slice (e[BMxD] . c[BNxD]^T) with fused online
// logsumexp per row over this block's V-slice. Each (row-tile, slice) pair is
// owned by exactly one block -> deterministic scratch writes, no atomics.
// ---------------------------------------------------------------------------
__global__ __launch_bounds__(256)
void k_lse_partial(const float* __restrict__ e, const float* __restrict__ c)
{
    __shared__ float As[BK][BM];
    __shared__ float Bs[BK][BN];
    __shared__ float red_m[BM][16];
    __shared__ float red_s[BM][16];

    const int tid = threadIdx.x;
    const int tx  = tid & 15;        // column group 0..15
    const int ty  = tid >> 4;        // row group 0..15
    const int row0    = blockIdx.x * BM;
    const int slice   = blockIdx.y;
    const int v_begin = slice * SLICE_W;
    const int v_end   = min(v_begin + SLICE_W, VOCAB);

    float m[8], s[8];
#pragma unroll
    for (int i = 0; i < 8; i++) { m[i] = -INFINITY; s[i] = 0.0f; }

    for (int col0 = v_begin; col0 < v_end; col0 += BN) {
        float acc[8][8];
#pragma unroll
        for (int i = 0; i < 8; i++)
#pragma unroll
            for (int j = 0; j < 8; j++) acc[i][j] = 0.0f;

        for (int k0 = 0; k0 < DIM; k0 += BK) {
            // Load A tile (128 rows x 16 k) as float4, store transposed
#pragma unroll
            for (int jj = 0; jj < 2; jj++) {
                int f  = tid + 256 * jj;       // 0..511 float4 slots
                int r  = f >> 2;               // 0..127
                int c4 = f & 3;                // 0..3
                float4 v = *(const float4*)(e + (size_t)(row0 + r) * DIM + k0 + c4 * 4);
                As[c4 * 4 + 0][r] = v.x;
                As[c4 * 4 + 1][r] = v.y;
                As[c4 * 4 + 2][r] = v.z;
                As[c4 * 4 + 3][r] = v.w;
            }
            // Load B tile (128 vocab rows x 16 k), zero-fill past VOCAB
#pragma unroll
            for (int jj = 0; jj < 2; jj++) {
                int f  = tid + 256 * jj;
                int r  = f >> 2;
                int c4 = f & 3;
                int gcol = col0 + r;
                float4 v = make_float4(0.f, 0.f, 0.f, 0.f);
                if (gcol < VOCAB)
                    v = *(const float4*)(c + (size_t)gcol * DIM + k0 + c4 * 4);
                Bs[c4 * 4 + 0][r] = v.x;
                Bs[c4 * 4 + 1][r] = v.y;
                Bs[c4 * 4 + 2][r] = v.z;
                Bs[c4 * 4 + 3][r] = v.w;
            }
            __syncthreads();

#pragma unroll
            for (int kk = 0; kk < BK; kk++) {
                float ra[8], rb[8];
                const float4* a4 = (const float4*)&As[kk][ty * 8];
                const float4* b4 = (const float4*)&Bs[kk][tx * 8];
                float4 a0 = a4[0], a1 = a4[1];
                float4 b0 = b4[0], b1 = b4[1];
                ra[0] = a0.x; ra[1] = a0.y; ra[2] = a0.z; ra[3] = a0.w;
                ra[4] = a1.x; ra[5] = a1.y; ra[6] = a1.z; ra[7] = a1.w;
                rb[0] = b0.x; rb[1] = b0.y; rb[2] = b0.z; rb[3] = b0.w;
                rb[4] = b1.x; rb[5] = b1.y; rb[6] = b1.z; rb[7] = b1.w;
#pragma unroll
                for (int i = 0; i < 8; i++)
#pragma unroll
                    for (int j = 0; j < 8; j++)
                        acc[i][j] = fmaf(ra[i], rb[j], acc[i][j]);
            }
            __syncthreads();
        }

        // Fused online logsumexp update over this BN tile (mask invalid cols)
#pragma unroll
        for (int i = 0; i < 8; i++) {
            float tmax = -INFINITY;
#pragma unroll
            for (int j = 0; j < 8; j++) {
                int gcol = col0 + tx * 8 + j;
                float v = (gcol < v_end) ? acc[i][j] : -INFINITY;
                acc[i][j] = v;
                tmax = fmaxf(tmax, v);
            }
            if (tmax > -INFINITY) {
                float newM = fmaxf(m[i], tmax);
                float add = 0.0f;
#pragma unroll
                for (int j = 0; j < 8; j++)
                    add += __expf(acc[i][j] - newM);   // exp(-inf)=0 handles mask
                s[i] = s[i] * __expf(m[i] - newM) + add;
                m[i] = newM;
            }
        }
    }

    // Reduce the 16 column-thread partials per row
#pragma unroll
    for (int i = 0; i < 8; i++) {
        red_m[ty * 8 + i][tx] = m[i];
        red_s[ty * 8 + i][tx] = s[i];
    }
    __syncthreads();

    if (tid < BM) {
        float M = -INFINITY, S = 0.0f;
#pragma unroll
        for (int j = 0; j < 16; j++) {
            float mj = red_m[tid][j];
            float sj = red_s[tid][j];
            if (mj > -INFINITY) {
                if (mj > M) { S = S * __expf(M - mj) + sj; M = mj; }
                else        { S += sj * __expf(mj - M); }
            }
        }
        g_pm[slice * N_TOK + row0 + tid] = M;
        g_ps[slice * N_TOK + row0 + tid] = S;
    }
}

// ---------------------------------------------------------------------------
// Kernel 2: per-row -> merge slice partials into lse, compute target logit
// (128-thread dot over D=1024), write nll[row].
// ---------------------------------------------------------------------------
__global__ __launch_bounds__(128)
void k_row_nll(const float* __restrict__ e, const float* __restrict__ c,
               const void* __restrict__ targets)
{
    const int row = blockIdx.x;
    __shared__ float sd[128];
    __shared__ bool s_is64;

    if (threadIdx.x == 0) s_is64 = targets_are_i64((const int*)targets);
    __syncthreads();

    long long t = get_target(targets, row, s_is64);
    bool valid = (t != IGNORE);
    int safe = valid ? (int)t : 0;

    const float* er = e + (size_t)row * DIM;
    const float* cr = c + (size_t)safe * DIM;
    float dot = 0.0f;
#pragma unroll
    for (int it = 0; it < DIM / 128; it++) {
        int i = threadIdx.x + it * 128;
        dot = fmaf(er[i], cr[i], dot);
    }
    sd[threadIdx.x] = dot;
    __syncthreads();
    for (int off = 64; off > 0; off >>= 1) {
        if (threadIdx.x < off) sd[threadIdx.x] += sd[threadIdx.x + off];
        __syncthreads();
    }

    if (threadIdx.x == 0) {
        float M = -INFINITY, S = 0.0f;
#pragma unroll
        for (int sl = 0; sl < NSLICES; sl++) {
            float mj = g_pm[sl * N_TOK + row];
            float sj = g_ps[sl * N_TOK + row];
            if (mj > -INFINITY) {
                if (mj > M) { S = S * expf(M - mj) + sj; M = mj; }
                else        { S += sj * expf(mj - M); }
            }
        }
        float lse = M + logf(S);
        g_nll[row] = valid ? (lse - sd[0]) : 0.0f;
    }
}

// ---------------------------------------------------------------------------
// Kernel 3: deterministic single-block reduction -> mean over valid rows
// ---------------------------------------------------------------------------
__global__ __launch_bounds__(1024)
void k_reduce(const void* __restrict__ targets, float* __restrict__ out)
{
    __shared__ float ss[1024];
    __shared__ float sc[1024];
    __shared__ bool  s_is64;
    if (threadIdx.x == 0) s_is64 = targets_are_i64((const int*)targets);
    __syncthreads();

    float sum = 0.0f, cnt = 0.0f;
    for (int r = threadIdx.x; r < N_TOK; r += 1024) {
        sum += g_nll[r];
        long long t = get_target(targets, r, s_is64);
        cnt += (t != IGNORE) ? 1.0f : 0.0f;
    }
    ss[threadIdx.x] = sum;
    sc[threadIdx.x] = cnt;
    __syncthreads();
    for (int off = 512; off > 0; off >>= 1) {
        if (threadIdx.x < off) {
            ss[threadIdx.x] += ss[threadIdx.x + off];
            sc[threadIdx.x] += sc[threadIdx.x + off];
        }
        __syncthreads();
    }
    if (threadIdx.x == 0)
        out[0] = ss[0] / fmaxf(sc[0], 1.0f);
}

// ---------------------------------------------------------------------------
extern "C" void kernel_launch(void* const* d_in, const int* in_sizes, int n_in,
                              void* d_out, int out_size)
{
    const float* e = (const float*)d_in[0];
    const float* c = (const float*)d_in[1];
    const void*  t = d_in[2];
    float* out = (float*)d_out;

    dim3 g1(N_TOK / BM, NSLICES);
    k_lse_partial<<<g1, 256>>>(e, c);
    k_row_nll<<<N_TOK, 128>>>(e, c, t);
    k_reduce<<<1, 1024>>>(t, out);
}

// round 3
// speedup vs baseline: 5.0690x; 5.0690x over previous
#include <cuda_runtime.h>
#include <math.h>
#include <stdint.h>

// ---------------------------------------------------------------------------
// Problem constants
// ---------------------------------------------------------------------------
#define N_TOK   8192
#define DIM     1024
#define VOCAB   50257
#define IGNORE  (-100)

// GEMM tiling
#define BM 128
#define BN 128
#define BK 32
#define NSTAGES 3
#define NSLICES 8
#define NTILES  ((VOCAB + BN - 1) / BN)    // 393
#define KCHUNKS (DIM / BK)                 // 32
#define NPART   (NSLICES * 2)              // 16 partial (m,s) sets per row

#define STAGE_A_BYTES (BM * BK * 4)        // 16 KB
#define STAGE_B_BYTES (BN * BK * 4)        // 16 KB
#define STAGE_BYTES   (STAGE_A_BYTES + STAGE_B_BYTES)
#define SMEM_BYTES    (NSTAGES * STAGE_BYTES)  // 96 KB

#define NEG_INF __int_as_float(0xff800000)

// ---------------------------------------------------------------------------
// Device scratch (allocation-free)
// ---------------------------------------------------------------------------
__device__ __align__(16) float g_e32[N_TOK * DIM];    // tf32-rounded e
__device__ __align__(16) float g_c32[VOCAB * DIM];    // tf32-rounded c
__device__ float g_pm[NPART * N_TOK];
__device__ float g_ps[NPART * N_TOK];
__device__ float g_nll[N_TOK];

// ---------------------------------------------------------------------------
// PTX helpers (all baseline ISA — must compile for compute_103 non-'a')
// ---------------------------------------------------------------------------
__device__ __forceinline__ uint32_t smem_u32(const void* p) {
    uint32_t a;
    asm("{ .reg .u64 t; cvta.to.shared.u64 t, %1; cvt.u32.u64 %0, t; }" : "=r"(a) : "l"(p));
    return a;
}
__device__ __forceinline__ void cp_async16(uint32_t dst, const void* src, int sz) {
    asm volatile("cp.async.cg.shared.global [%0], [%1], 16, %2;"
                 :: "r"(dst), "l"(src), "r"(sz));
}
__device__ __forceinline__ void ldsm4(uint32_t& r0, uint32_t& r1, uint32_t& r2,
                                      uint32_t& r3, uint32_t addr) {
    asm volatile("ldmatrix.sync.aligned.m8n8.x4.shared.b16 {%0,%1,%2,%3}, [%4];"
                 : "=r"(r0), "=r"(r1), "=r"(r2), "=r"(r3) : "r"(addr));
}
__device__ __forceinline__ void mma_tf32(float* c, const uint32_t* a, const uint32_t* b) {
    asm volatile(
        "mma.sync.aligned.m16n8k8.row.col.f32.tf32.tf32.f32 "
        "{%0,%1,%2,%3}, {%4,%5,%6,%7}, {%8,%9}, {%0,%1,%2,%3};"
        : "+f"(c[0]), "+f"(c[1]), "+f"(c[2]), "+f"(c[3])
        : "r"(a[0]), "r"(a[1]), "r"(a[2]), "r"(a[3]), "r"(b[0]), "r"(b[1]));
}

// ---------------------------------------------------------------------------
// Pre-pass: fp32 -> tf32 round-to-nearest (MMA truncation then exact: no bias)
// ---------------------------------------------------------------------------
__global__ void k_cvt(const float4* __restrict__ in, float4* __restrict__ out, int n4) {
    int i = blockIdx.x * blockDim.x + threadIdx.x;
    if (i < n4) {
        float4 v = in[i];
        uint32_t a, b, c, d;
        asm("cvt.rna.tf32.f32 %0, %1;" : "=r"(a) : "f"(v.x));
        asm("cvt.rna.tf32.f32 %0, %1;" : "=r"(b) : "f"(v.y));
        asm("cvt.rna.tf32.f32 %0, %1;" : "=r"(c) : "f"(v.z));
        asm("cvt.rna.tf32.f32 %0, %1;" : "=r"(d) : "f"(v.w));
        float4 o;
        o.x = __uint_as_float(a); o.y = __uint_as_float(b);
        o.z = __uint_as_float(c); o.w = __uint_as_float(d);
        out[i] = o;
    }
}

// ---------------------------------------------------------------------------
// Main fused GEMM (mma.sync tf32) + online logsumexp.
// Grid (64 row-tiles, 8 slices), 256 threads = 8 warps in a 4(m) x 2(n) grid.
// Warp tile 32x64: 2 m16-tiles x 8 n8-tiles. Slice s owns vocab tiles
// {s, s+8, s+16, ...} (round-robin for balance).
// ---------------------------------------------------------------------------
__global__ void __launch_bounds__(256, 2)
k_cce(const float* __restrict__ ge, const float* __restrict__ gc)
{
    extern __shared__ char smem[];
    const uint32_t sb = smem_u32(smem);
    const int tid  = threadIdx.x;
    const int lane = tid & 31;
    const int wid  = tid >> 5;
    const int warp_m = wid & 3;
    const int warp_n = wid >> 2;
    const int row0  = blockIdx.x * BM;
    const int slice = blockIdx.y;
    const int ntiles = (NTILES - slice + NSLICES - 1) / NSLICES;
    const int S = ntiles * KCHUNKS;

    // cp.async per-thread layout: 4 chunks of 16B for A and B each.
    const int ar = tid >> 3;            // 0..31
    const int ac = tid & 7;             // 16B chunk col 0..7
    const uint32_t st_off = ar * 128 + ((ac ^ (ar & 7)) << 4);
    const float* gA0 = ge + (size_t)(row0 + ar) * DIM + ac * 4;

    // ldmatrix per-thread addressing
    const int rA0 = warp_m * 32 + (lane & 15);
    const uint32_t aoff0 = rA0 * 128;
    const uint32_t aoff1 = (rA0 + 16) * 128;
    const uint32_t asw   = rA0 & 7;          // same for both m-tiles (+16 == 0 mod 8)
    const int ahi = lane >> 4;
    const int rB  = ((lane >> 4) << 3) + (lane & 7);   // 0..15
    uint32_t boff[4];
#pragma unroll
    for (int p = 0; p < 4; p++) boff[p] = (warp_n * 64 + p * 16 + rB) * 128;
    const uint32_t bsw = lane & 7;
    const int bhi = (lane >> 3) & 1;

    // ---- stage loader ----
    auto load_stage = [&](int s, int buf) {
        const int kc   = s & (KCHUNKS - 1);
        const int tix  = slice + (s >> 5) * NSLICES;   // global vocab tile
        const int col0 = tix * BN;
        const uint32_t as = sb + buf * STAGE_BYTES;
        const uint32_t bs = as + STAGE_A_BYTES;
        const float* ga = gA0 + kc * BK;
#pragma unroll
        for (int i = 0; i < 4; i++)
            cp_async16(as + st_off + i * 4096, ga + (size_t)i * 32 * DIM, 16);
        const int vr0 = col0 + ar;
#pragma unroll
        for (int i = 0; i < 4; i++) {
            int vr = vr0 + i * 32;
            int ok = vr < VOCAB;
            const float* gb = gc + (size_t)(ok ? vr : 0) * DIM + kc * BK + ac * 4;
            cp_async16(bs + st_off + i * 4096, gb, ok ? 16 : 0);
        }
    };

    // ---- pipeline prologue ----
    int s_issue = 0, buf_issue = 0;
#pragma unroll
    for (int i = 0; i < NSTAGES - 1; i++) {
        load_stage(s_issue, buf_issue);
        asm volatile("cp.async.commit_group;" ::: "memory");
        s_issue++;
        buf_issue = (buf_issue == NSTAGES - 1) ? 0 : buf_issue + 1;
    }

    float msta[4], ssta[4];
#pragma unroll
    for (int i = 0; i < 4; i++) { msta[i] = NEG_INF; ssta[i] = 0.0f; }

    int buf_c = 0;
    for (int tt = 0; tt < ntiles; tt++) {
        const int tix  = slice + tt * NSLICES;
        const int col0 = tix * BN;
        const bool boundary = (tix == NTILES - 1);

        float acc[2][8][4];
#pragma unroll
        for (int mt = 0; mt < 2; mt++)
#pragma unroll
            for (int nt = 0; nt < 8; nt++)
#pragma unroll
                for (int k = 0; k < 4; k++) acc[mt][nt][k] = 0.0f;

#pragma unroll 1
        for (int kc = 0; kc < KCHUNKS; kc++) {
            asm volatile("cp.async.wait_group 1;" ::: "memory");
            __syncthreads();
            if (s_issue < S) load_stage(s_issue, buf_issue);
            asm volatile("cp.async.commit_group;" ::: "memory");
            s_issue++;
            buf_issue = (buf_issue == NSTAGES - 1) ? 0 : buf_issue + 1;

            const uint32_t as = sb + buf_c * STAGE_BYTES;
            const uint32_t bs = as + STAGE_A_BYTES;
#pragma unroll
            for (int ks = 0; ks < 4; ks++) {
                uint32_t af[2][4], bf[8][2];
                const uint32_t ach = (uint32_t)(2 * ks + ahi);
                ldsm4(af[0][0], af[0][1], af[0][2], af[0][3],
                      as + aoff0 + ((ach ^ asw) << 4));
                ldsm4(af[1][0], af[1][1], af[1][2], af[1][3],
                      as + aoff1 + ((ach ^ asw) << 4));
                const uint32_t bch = (uint32_t)(2 * ks + bhi);
#pragma unroll
                for (int p = 0; p < 4; p++)
                    ldsm4(bf[2 * p][0], bf[2 * p][1], bf[2 * p + 1][0], bf[2 * p + 1][1],
                          bs + boff[p] + ((bch ^ bsw) << 4));
#pragma unroll
                for (int mt = 0; mt < 2; mt++)
#pragma unroll
                    for (int nt = 0; nt < 8; nt++)
                        mma_tf32(acc[mt][nt], af[mt], bf[nt]);
            }
            buf_c = (buf_c == NSTAGES - 1) ? 0 : buf_c + 1;
        }

        // ---- fused online-logsumexp epilogue on register fragments ----
        const int colt = col0 + warp_n * 64 + 2 * (lane & 3);
#pragma unroll
        for (int mt = 0; mt < 2; mt++) {
#pragma unroll
            for (int h = 0; h < 2; h++) {
                const int rg = mt * 2 + h;
                float tmax = NEG_INF;
#pragma unroll
                for (int nt = 0; nt < 8; nt++)
#pragma unroll
                    for (int j = 0; j < 2; j++) {
                        float v = acc[mt][nt][h * 2 + j];
                        if (boundary && (colt + nt * 8 + j) >= VOCAB) v = NEG_INF;
                        tmax = fmaxf(tmax, v);
                    }
                const float nm = fmaxf(msta[rg], tmax);
                float add = 0.0f;
#pragma unroll
                for (int nt = 0; nt < 8; nt++)
#pragma unroll
                    for (int j = 0; j < 2; j++) {
                        float v = acc[mt][nt][h * 2 + j];
                        if (boundary && (colt + nt * 8 + j) >= VOCAB) v = NEG_INF;
                        add += __expf(v - nm);
                    }
                ssta[rg] = ssta[rg] * __expf(msta[rg] - nm) + add;
                msta[rg] = nm;
            }
        }
    }
    asm volatile("cp.async.wait_group 0;" ::: "memory");

    // ---- merge across the 4 lanes of each quad, store per (slice, warp_n) ----
#pragma unroll
    for (int rg = 0; rg < 4; rg++) {
        float m = msta[rg], s = ssta[rg];
#pragma unroll
        for (int off = 1; off <= 2; off <<= 1) {
            float om = __shfl_xor_sync(0xffffffffu, m, off);
            float os = __shfl_xor_sync(0xffffffffu, s, off);
            float nm = fmaxf(m, om);
            s = s * __expf(m - nm) + os * __expf(om - nm);
            m = nm;
        }
        if ((lane & 3) == 0) {
            const int row = row0 + warp_m * 32 + (rg >> 1) * 16 + (rg & 1) * 8 + (lane >> 2);
            const int p = slice * 2 + warp_n;
            g_pm[p * N_TOK + row] = m;
            g_ps[p * N_TOK + row] = s;
        }
    }
}

// ---------------------------------------------------------------------------
// Target dtype sniffing (int64 vs int32)
// ---------------------------------------------------------------------------
__device__ __forceinline__ bool targets_are_i64(const int* t32) {
#pragma unroll
    for (int j = 1; j < 64; j += 2) {
        int w = t32[j];
        if (w != 0 && w != -1) return false;
    }
    return true;
}
__device__ __forceinline__ long long get_target(const void* tp, int row, bool is64) {
    if (is64) return ((const long long*)tp)[row];
    return (long long)((const int*)tp)[row];
}

// ---------------------------------------------------------------------------
// Kernel 2: merge 16 partials -> lse; exact fp32 target dot; nll[row]
// ---------------------------------------------------------------------------
__global__ __launch_bounds__(128)
void k_row_nll(const float* __restrict__ e, const float* __restrict__ c,
               const void* __restrict__ targets)
{
    const int row = blockIdx.x;
    __shared__ float sd[128];
    __shared__ bool s_is64;
    if (threadIdx.x == 0) s_is64 = targets_are_i64((const int*)targets);
    __syncthreads();

    long long t = get_target(targets, row, s_is64);
    bool valid = (t != IGNORE);
    int safe = valid ? (int)t : 0;

    const float* er = e + (size_t)row * DIM;
    const float* cr = c + (size_t)safe * DIM;
    float dot = 0.0f;
#pragma unroll
    for (int it = 0; it < DIM / 128; it++) {
        int i = threadIdx.x + it * 128;
        dot = fmaf(er[i], cr[i], dot);
    }
    sd[threadIdx.x] = dot;
    __syncthreads();
    for (int off = 64; off > 0; off >>= 1) {
        if (threadIdx.x < off) sd[threadIdx.x] += sd[threadIdx.x + off];
        __syncthreads();
    }
    if (threadIdx.x == 0) {
        float M = NEG_INF, S = 0.0f;
#pragma unroll
        for (int p = 0; p < NPART; p++) {
            float mj = g_pm[p * N_TOK + row];
            float sj = g_ps[p * N_TOK + row];
            if (mj > NEG_INF) {
                if (mj > M) { S = S * expf(M - mj) + sj; M = mj; }
                else        { S += sj * expf(mj - M); }
            }
        }
        float lse = M + logf(S);
        g_nll[row] = valid ? (lse - sd[0]) : 0.0f;
    }
}

// ---------------------------------------------------------------------------
// Kernel 3: deterministic mean over valid rows
// ---------------------------------------------------------------------------
__global__ __launch_bounds__(1024)
void k_reduce(const void* __restrict__ targets, float* __restrict__ out)
{
    __shared__ float ss[1024];
    __shared__ float sc[1024];
    __shared__ bool  s_is64;
    if (threadIdx.x == 0) s_is64 = targets_are_i64((const int*)targets);
    __syncthreads();

    float sum = 0.0f, cnt = 0.0f;
    for (int r = threadIdx.x; r < N_TOK; r += 1024) {
        sum += g_nll[r];
        long long t = get_target(targets, r, s_is64);
        cnt += (t != IGNORE) ? 1.0f : 0.0f;
    }
    ss[threadIdx.x] = sum;
    sc[threadIdx.x] = cnt;
    __syncthreads();
    for (int off = 512; off > 0; off >>= 1) {
        if (threadIdx.x < off) {
            ss[threadIdx.x] += ss[threadIdx.x + off];
            sc[threadIdx.x] += sc[threadIdx.x + off];
        }
        __syncthreads();
    }
    if (threadIdx.x == 0)
        out[0] = ss[0] / fmaxf(sc[0], 1.0f);
}

// ---------------------------------------------------------------------------
// Host launcher
// ---------------------------------------------------------------------------
extern "C" void kernel_launch(void* const* d_in, const int* in_sizes, int n_in,
                              void* d_out, int out_size)
{
    const float* e = (const float*)d_in[0];
    const float* c = (const float*)d_in[1];
    const void*  t = d_in[2];
    float* out = (float*)d_out;

    void* pe = nullptr; void* pc = nullptr;
    cudaGetSymbolAddress(&pe, g_e32);
    cudaGetSymbolAddress(&pc, g_c32);

    // Pre-round inputs to tf32 (RNA)
    {
        int n4e = (N_TOK * DIM) / 4;
        int n4c = (VOCAB * DIM) / 4;
        k_cvt<<<(n4e + 255) / 256, 256>>>((const float4*)e, (float4*)pe, n4e);
        k_cvt<<<(n4c + 255) / 256, 256>>>((const float4*)c, (float4*)pc, n4c);
    }

    static int smem_set = 0;
    if (!smem_set) {
        cudaFuncSetAttribute(k_cce, cudaFuncAttributeMaxDynamicSharedMemorySize, SMEM_BYTES);
        smem_set = 1;
    }
    dim3 grid(N_TOK / BM, NSLICES);
    k_cce<<<grid, 256, SMEM_BYTES>>>((const float*)pe, (const float*)pc);

    k_row_nll<<<N_TOK, 128>>>(e, c, t);
    k_reduce<<<1, 1024>>>(t, out);
}

// round 4
// speedup vs baseline: 9.6587x; 1.9054x over previous
#include <cuda_runtime.h>
#include <cuda_bf16.h>
#include <math.h>
#include <stdint.h>

// ---------------------------------------------------------------------------
// Problem constants
// ---------------------------------------------------------------------------
#define N_TOK   8192
#define DIM     1024
#define VOCAB   50257
#define IGNORE  (-100)

// GEMM tiling (bf16: 128-byte SMEM rows = 64 k-elements)
#define BM 128
#define BN 128
#define BKE 64                              // k elements per stage
#define NSTAGES 3
#define NSLICES 8
#define NTILES  ((VOCAB + BN - 1) / BN)     // 393
#define KCHUNKS (DIM / BKE)                 // 16
#define NPART   (NSLICES * 2)

#define STAGE_A_BYTES (BM * BKE * 2)        // 16 KB
#define STAGE_B_BYTES (BN * BKE * 2)        // 16 KB
#define STAGE_BYTES   (STAGE_A_BYTES + STAGE_B_BYTES)
#define SMEM_BYTES    (NSTAGES * STAGE_BYTES)   // 96 KB

#define NEG_INF __int_as_float(0xff800000)

// ---------------------------------------------------------------------------
// Device scratch (allocation-free)
// ---------------------------------------------------------------------------
__device__ __align__(16) __nv_bfloat16 g_e16[N_TOK * DIM];
__device__ __align__(16) __nv_bfloat16 g_c16[VOCAB * DIM];
__device__ float g_pm[NPART * N_TOK];
__device__ float g_ps[NPART * N_TOK];
__device__ float g_nll[N_TOK];

// ---------------------------------------------------------------------------
// PTX helpers (baseline ISA only — compiles under compute_103 non-'a')
// ---------------------------------------------------------------------------
__device__ __forceinline__ uint32_t smem_u32(const void* p) {
    uint32_t a;
    asm("{ .reg .u64 t; cvta.to.shared.u64 t, %1; cvt.u32.u64 %0, t; }" : "=r"(a) : "l"(p));
    return a;
}
__device__ __forceinline__ void cp_async16(uint32_t dst, const void* src, int sz) {
    asm volatile("cp.async.cg.shared.global [%0], [%1], 16, %2;"
                 :: "r"(dst), "l"(src), "r"(sz));
}
__device__ __forceinline__ void ldsm4(uint32_t& r0, uint32_t& r1, uint32_t& r2,
                                      uint32_t& r3, uint32_t addr) {
    asm volatile("ldmatrix.sync.aligned.m8n8.x4.shared.b16 {%0,%1,%2,%3}, [%4];"
                 : "=r"(r0), "=r"(r1), "=r"(r2), "=r"(r3) : "r"(addr));
}
__device__ __forceinline__ void mma_bf16(float* c, const uint32_t* a, const uint32_t* b) {
    asm volatile(
        "mma.sync.aligned.m16n8k16.row.col.f32.bf16.bf16.f32 "
        "{%0,%1,%2,%3}, {%4,%5,%6,%7}, {%8,%9}, {%0,%1,%2,%3};"
        : "+f"(c[0]), "+f"(c[1]), "+f"(c[2]), "+f"(c[3])
        : "r"(a[0]), "r"(a[1]), "r"(a[2]), "r"(a[3]), "r"(b[0]), "r"(b[1]));
}

// ---------------------------------------------------------------------------
// Pre-pass: fp32 -> bf16 round-to-nearest. 8 elements / thread.
// ---------------------------------------------------------------------------
__global__ void k_cvt(const float4* __restrict__ in, uint4* __restrict__ out, int n8) {
    int i = blockIdx.x * blockDim.x + threadIdx.x;
    if (i < n8) {
        float4 v0 = in[2 * i];
        float4 v1 = in[2 * i + 1];
        __nv_bfloat162 b0 = __float22bfloat162_rn(make_float2(v0.x, v0.y));
        __nv_bfloat162 b1 = __float22bfloat162_rn(make_float2(v0.z, v0.w));
        __nv_bfloat162 b2 = __float22bfloat162_rn(make_float2(v1.x, v1.y));
        __nv_bfloat162 b3 = __float22bfloat162_rn(make_float2(v1.z, v1.w));
        uint4 o;
        o.x = *(uint32_t*)&b0; o.y = *(uint32_t*)&b1;
        o.z = *(uint32_t*)&b2; o.w = *(uint32_t*)&b3;
        out[i] = o;
    }
}

// ---------------------------------------------------------------------------
// Main fused GEMM (mma.sync bf16 m16n8k16) + online logsumexp.
// Grid (64 row-tiles, 8 slices), 256 threads = 8 warps (4m x 2n), 32x64 warp
// tiles. Slice s owns vocab tiles {s, s+8, ...}. Byte-level SMEM addressing
// is identical to the validated tf32 round (128B rows, XOR-16B swizzle).
// ---------------------------------------------------------------------------
__global__ void __launch_bounds__(256, 2)
k_cce(const __nv_bfloat16* __restrict__ ge, const __nv_bfloat16* __restrict__ gc)
{
    extern __shared__ char smem[];
    const uint32_t sb = smem_u32(smem);
    const int tid  = threadIdx.x;
    const int lane = tid & 31;
    const int wid  = tid >> 5;
    const int warp_m = wid & 3;
    const int warp_n = wid >> 2;
    const int row0  = blockIdx.x * BM;
    const int slice = blockIdx.y;
    const int ntiles = (NTILES - slice + NSLICES - 1) / NSLICES;
    const int S = ntiles * KCHUNKS;

    // cp.async per-thread layout: 32 rows x 8 chunks(16B); 4 row-iterations.
    const int ar = tid >> 3;
    const int ac = tid & 7;
    const uint32_t st_off = ar * 128 + ((ac ^ (ar & 7)) << 4);
    const __nv_bfloat16* gA0 = ge + (size_t)(row0 + ar) * DIM + ac * 8;

    // ldmatrix addressing (bytes — identical pattern to tf32 round)
    const int rA0 = warp_m * 32 + (lane & 15);
    const uint32_t aoff0 = rA0 * 128;
    const uint32_t aoff1 = (rA0 + 16) * 128;
    const uint32_t asw   = rA0 & 7;
    const int ahi = lane >> 4;                       // k-half chunk
    const int rB  = ((lane >> 4) << 3) + (lane & 7); // n-row within 16
    uint32_t boff[4];
#pragma unroll
    for (int p = 0; p < 4; p++) boff[p] = (warp_n * 64 + p * 16 + rB) * 128;
    const uint32_t bsw = lane & 7;
    const int bhi = (lane >> 3) & 1;                 // k-half chunk

    // ---- stage loader ----
    auto load_stage = [&](int s, int buf) {
        const int kc   = s & (KCHUNKS - 1);
        const int tix  = slice + (s >> 4) * NSLICES;
        const int col0 = tix * BN;
        const uint32_t as = sb + buf * STAGE_BYTES;
        const uint32_t bs = as + STAGE_A_BYTES;
        const __nv_bfloat16* ga = gA0 + kc * BKE;
#pragma unroll
        for (int i = 0; i < 4; i++)
            cp_async16(as + st_off + i * 4096, ga + (size_t)i * 32 * DIM, 16);
        const int vr0 = col0 + ar;
#pragma unroll
        for (int i = 0; i < 4; i++) {
            int vr = vr0 + i * 32;
            int ok = vr < VOCAB;
            const __nv_bfloat16* gb = gc + (size_t)(ok ? vr : 0) * DIM + kc * BKE + ac * 8;
            cp_async16(bs + st_off + i * 4096, gb, ok ? 16 : 0);  // sz=0 zero-fills
        }
    };

    // ---- pipeline prologue ----
    int s_issue = 0, buf_issue = 0;
#pragma unroll
    for (int i = 0; i < NSTAGES - 1; i++) {
        load_stage(s_issue, buf_issue);
        asm volatile("cp.async.commit_group;" ::: "memory");
        s_issue++;
        buf_issue = (buf_issue == NSTAGES - 1) ? 0 : buf_issue + 1;
    }

    float msta[4], ssta[4];
#pragma unroll
    for (int i = 0; i < 4; i++) { msta[i] = NEG_INF; ssta[i] = 0.0f; }

    int buf_c = 0;
    for (int tt = 0; tt < ntiles; tt++) {
        const int tix  = slice + tt * NSLICES;
        const int col0 = tix * BN;
        const bool boundary = (tix == NTILES - 1);

        float acc[2][8][4];
#pragma unroll
        for (int mt = 0; mt < 2; mt++)
#pragma unroll
            for (int nt = 0; nt < 8; nt++)
#pragma unroll
                for (int k = 0; k < 4; k++) acc[mt][nt][k] = 0.0f;

#pragma unroll 1
        for (int kc = 0; kc < KCHUNKS; kc++) {
            asm volatile("cp.async.wait_group 1;" ::: "memory");
            __syncthreads();
            if (s_issue < S) load_stage(s_issue, buf_issue);
            asm volatile("cp.async.commit_group;" ::: "memory");
            s_issue++;
            buf_issue = (buf_issue == NSTAGES - 1) ? 0 : buf_issue + 1;

            const uint32_t as = sb + buf_c * STAGE_BYTES;
            const uint32_t bs = as + STAGE_A_BYTES;
#pragma unroll
            for (int ks = 0; ks < 4; ks++) {      // 4 x k16 per 64-elt chunk
                uint32_t af[2][4], bf[8][2];
                const uint32_t ach = (uint32_t)(2 * ks + ahi);
                ldsm4(af[0][0], af[0][1], af[0][2], af[0][3],
                      as + aoff0 + ((ach ^ asw) << 4));
                ldsm4(af[1][0], af[1][1], af[1][2], af[1][3],
                      as + aoff1 + ((ach ^ asw) << 4));
                const uint32_t bch = (uint32_t)(2 * ks + bhi);
#pragma unroll
                for (int p = 0; p < 4; p++)
                    ldsm4(bf[2 * p][0], bf[2 * p][1], bf[2 * p + 1][0], bf[2 * p + 1][1],
                          bs + boff[p] + ((bch ^ bsw) << 4));
#pragma unroll
                for (int mt = 0; mt < 2; mt++)
#pragma unroll
                    for (int nt = 0; nt < 8; nt++)
                        mma_bf16(acc[mt][nt], af[mt], bf[nt]);
            }
            buf_c = (buf_c == NSTAGES - 1) ? 0 : buf_c + 1;
        }

        // ---- fused online-logsumexp epilogue on register fragments ----
        const int colt = col0 + warp_n * 64 + 2 * (lane & 3);
#pragma unroll
        for (int mt = 0; mt < 2; mt++) {
#pragma unroll
            for (int h = 0; h < 2; h++) {
                const int rg = mt * 2 + h;
                float tmax = NEG_INF;
#pragma unroll
                for (int nt = 0; nt < 8; nt++)
#pragma unroll
                    for (int j = 0; j < 2; j++) {
                        float v = acc[mt][nt][h * 2 + j];
                        if (boundary && (colt + nt * 8 + j) >= VOCAB) v = NEG_INF;
                        tmax = fmaxf(tmax, v);
                    }
                const float nm = fmaxf(msta[rg], tmax);
                float add = 0.0f;
#pragma unroll
                for (int nt = 0; nt < 8; nt++)
#pragma unroll
                    for (int j = 0; j < 2; j++) {
                        float v = acc[mt][nt][h * 2 + j];
                        if (boundary && (colt + nt * 8 + j) >= VOCAB) v = NEG_INF;
                        add += __expf(v - nm);
                    }
                ssta[rg] = ssta[rg] * __expf(msta[rg] - nm) + add;
                msta[rg] = nm;
            }
        }
    }
    asm volatile("cp.async.wait_group 0;" ::: "memory");

    // ---- merge the 4 lanes of each quad; store per (slice, warp_n) ----
#pragma unroll
    for (int rg = 0; rg < 4; rg++) {
        float m = msta[rg], s = ssta[rg];
#pragma unroll
        for (int off = 1; off <= 2; off <<= 1) {
            float om = __shfl_xor_sync(0xffffffffu, m, off);
            float os = __shfl_xor_sync(0xffffffffu, s, off);
            float nm = fmaxf(m, om);
            s = s * __expf(m - nm) + os * __expf(om - nm);
            m = nm;
        }
        if ((lane & 3) == 0) {
            const int row = row0 + warp_m * 32 + (rg >> 1) * 16 + (rg & 1) * 8 + (lane >> 2);
            const int p = slice * 2 + warp_n;
            g_pm[p * N_TOK + row] = m;
            g_ps[p * N_TOK + row] = s;
        }
    }
}

// ---------------------------------------------------------------------------
// Target dtype sniffing (int64 vs int32)
// ---------------------------------------------------------------------------
__device__ __forceinline__ bool targets_are_i64(const int* t32) {
#pragma unroll
    for (int j = 1; j < 64; j += 2) {
        int w = t32[j];
        if (w != 0 && w != -1) return false;
    }
    return true;
}
__device__ __forceinline__ long long get_target(const void* tp, int row, bool is64) {
    if (is64) return ((const long long*)tp)[row];
    return (long long)((const int*)tp)[row];
}

// ---------------------------------------------------------------------------
// Kernel 2: merge 16 partials -> lse; exact fp32 target dot; nll[row]
// ---------------------------------------------------------------------------
__global__ __launch_bounds__(128)
void k_row_nll(const float* __restrict__ e, const float* __restrict__ c,
               const void* __restrict__ targets)
{
    const int row = blockIdx.x;
    __shared__ float sd[128];
    __shared__ bool s_is64;
    if (threadIdx.x == 0) s_is64 = targets_are_i64((const int*)targets);
    __syncthreads();

    long long t = get_target(targets, row, s_is64);
    bool valid = (t != IGNORE);
    int safe = valid ? (int)t : 0;

    const float* er = e + (size_t)row * DIM;
    const float* cr = c + (size_t)safe * DIM;
    float dot = 0.0f;
#pragma unroll
    for (int it = 0; it < DIM / 128; it++) {
        int i = threadIdx.x + it * 128;
        dot = fmaf(er[i], cr[i], dot);
    }
    sd[threadIdx.x] = dot;
    __syncthreads();
    for (int off = 64; off > 0; off >>= 1) {
        if (threadIdx.x < off) sd[threadIdx.x] += sd[threadIdx.x + off];
        __syncthreads();
    }
    if (threadIdx.x == 0) {
        float M = NEG_INF, S = 0.0f;
#pragma unroll
        for (int p = 0; p < NPART; p++) {
            float mj = g_pm[p * N_TOK + row];
            float sj = g_ps[p * N_TOK + row];
            if (mj > NEG_INF) {
                if (mj > M) { S = S * expf(M - mj) + sj; M = mj; }
                else        { S += sj * expf(mj - M); }
            }
        }
        float lse = M + logf(S);
        g_nll[row] = valid ? (lse - sd[0]) : 0.0f;
    }
}

// ---------------------------------------------------------------------------
// Kernel 3: deterministic mean over valid rows
// ---------------------------------------------------------------------------
__global__ __launch_bounds__(1024)
void k_reduce(const void* __restrict__ targets, float* __restrict__ out)
{
    __shared__ float ss[1024];
    __shared__ float sc[1024];
    __shared__ bool  s_is64;
    if (threadIdx.x == 0) s_is64 = targets_are_i64((const int*)targets);
    __syncthreads();

    float sum = 0.0f, cnt = 0.0f;
    for (int r = threadIdx.x; r < N_TOK; r += 1024) {
        sum += g_nll[r];
        long long t = get_target(targets, r, s_is64);
        cnt += (t != IGNORE) ? 1.0f : 0.0f;
    }
    ss[threadIdx.x] = sum;
    sc[threadIdx.x] = cnt;
    __syncthreads();
    for (int off = 512; off > 0; off >>= 1) {
        if (threadIdx.x < off) {
            ss[threadIdx.x] += ss[threadIdx.x + off];
            sc[threadIdx.x] += sc[threadIdx.x + off];
        }
        __syncthreads();
    }
    if (threadIdx.x == 0)
        out[0] = ss[0] / fmaxf(sc[0], 1.0f);
}

// ---------------------------------------------------------------------------
// Host launcher
// ---------------------------------------------------------------------------
extern "C" void kernel_launch(void* const* d_in, const int* in_sizes, int n_in,
                              void* d_out, int out_size)
{
    const float* e = (const float*)d_in[0];
    const float* c = (const float*)d_in[1];
    const void*  t = d_in[2];
    float* out = (float*)d_out;

    void* pe = nullptr; void* pc = nullptr;
    cudaGetSymbolAddress(&pe, g_e16);
    cudaGetSymbolAddress(&pc, g_c16);

    // Pre-round inputs to bf16 (RN)
    {
        int n8e = (N_TOK * DIM) / 8;
        int n8c = (VOCAB * DIM) / 8;
        k_cvt<<<(n8e + 255) / 256, 256>>>((const float4*)e, (uint4*)pe, n8e);
        k_cvt<<<(n8c + 255) / 256, 256>>>((const float4*)c, (uint4*)pc, n8c);
    }

    static int smem_set = 0;
    if (!smem_set) {
        cudaFuncSetAttribute(k_cce, cudaFuncAttributeMaxDynamicSharedMemorySize, SMEM_BYTES);
        smem_set = 1;
    }
    dim3 grid(N_TOK / BM, NSLICES);
    k_cce<<<grid, 256, SMEM_BYTES>>>((const __nv_bfloat16*)pe, (const __nv_bfloat16*)pc);

    k_row_nll<<<N_TOK, 128>>>(e, c, t);
    k_reduce<<<1, 1024>>>(t, out);
}

// round 5
// speedup vs baseline: 11.4855x; 1.1891x over previous
#include <cuda_runtime.h>
#include <cuda_bf16.h>
#include <math.h>
#include <stdint.h>

// ---------------------------------------------------------------------------
// Problem constants
// ---------------------------------------------------------------------------
#define N_TOK   8192
#define DIM     1024
#define VOCAB   50257
#define IGNORE  (-100)

// GEMM tiling (bf16: 128-byte SMEM rows = 64 k-elements)
#define BM 128
#define BN 128
#define BKE 64                              // k elements per stage
#define NSTAGES 3
#define NSLICES 37                          // 64*37 = 2368 = 8 * (148 SM * 2 CTA)
#define NTILES  ((VOCAB + BN - 1) / BN)     // 393
#define KCHUNKS (DIM / BKE)                 // 16
#define NPART   (NSLICES * 2)               // 74

#define STAGE_A_BYTES (BM * BKE * 2)        // 16 KB
#define STAGE_B_BYTES (BN * BKE * 2)        // 16 KB
#define STAGE_BYTES   (STAGE_A_BYTES + STAGE_B_BYTES)
#define SMEM_BYTES    (NSTAGES * STAGE_BYTES)   // 96 KB

#define NEG_INF __int_as_float(0xff800000)

// ---------------------------------------------------------------------------
// Device scratch (allocation-free)
// ---------------------------------------------------------------------------
__device__ __align__(16) __nv_bfloat16 g_e16[N_TOK * DIM];
__device__ __align__(16) __nv_bfloat16 g_c16[VOCAB * DIM];
__device__ float g_pm[NPART * N_TOK];
__device__ float g_ps[NPART * N_TOK];
__device__ float g_nll[N_TOK];

// ---------------------------------------------------------------------------
// PTX helpers (baseline ISA only — compiles under compute_103 non-'a')
// ---------------------------------------------------------------------------
__device__ __forceinline__ uint32_t smem_u32(const void* p) {
    uint32_t a;
    asm("{ .reg .u64 t; cvta.to.shared.u64 t, %1; cvt.u32.u64 %0, t; }" : "=r"(a) : "l"(p));
    return a;
}
__device__ __forceinline__ void cp_async16(uint32_t dst, const void* src, int sz) {
    asm volatile("cp.async.cg.shared.global [%0], [%1], 16, %2;"
                 :: "r"(dst), "l"(src), "r"(sz));
}
__device__ __forceinline__ void ldsm4(uint32_t& r0, uint32_t& r1, uint32_t& r2,
                                      uint32_t& r3, uint32_t addr) {
    asm volatile("ldmatrix.sync.aligned.m8n8.x4.shared.b16 {%0,%1,%2,%3}, [%4];"
                 : "=r"(r0), "=r"(r1), "=r"(r2), "=r"(r3) : "r"(addr));
}
__device__ __forceinline__ void mma_bf16(float* c, const uint32_t* a, const uint32_t* b) {
    asm volatile(
        "mma.sync.aligned.m16n8k16.row.col.f32.bf16.bf16.f32 "
        "{%0,%1,%2,%3}, {%4,%5,%6,%7}, {%8,%9}, {%0,%1,%2,%3};"
        : "+f"(c[0]), "+f"(c[1]), "+f"(c[2]), "+f"(c[3])
        : "r"(a[0]), "r"(a[1]), "r"(a[2]), "r"(a[3]), "r"(b[0]), "r"(b[1]));
}

// ---------------------------------------------------------------------------
// Pre-pass: fp32 -> bf16 round-to-nearest. 8 elements / thread.
// ---------------------------------------------------------------------------
__global__ void k_cvt(const float4* __restrict__ in, uint4* __restrict__ out, int n8) {
    int i = blockIdx.x * blockDim.x + threadIdx.x;
    if (i < n8) {
        float4 v0 = in[2 * i];
        float4 v1 = in[2 * i + 1];
        __nv_bfloat162 b0 = __float22bfloat162_rn(make_float2(v0.x, v0.y));
        __nv_bfloat162 b1 = __float22bfloat162_rn(make_float2(v0.z, v0.w));
        __nv_bfloat162 b2 = __float22bfloat162_rn(make_float2(v1.x, v1.y));
        __nv_bfloat162 b3 = __float22bfloat162_rn(make_float2(v1.z, v1.w));
        uint4 o;
        o.x = *(uint32_t*)&b0; o.y = *(uint32_t*)&b1;
        o.z = *(uint32_t*)&b2; o.w = *(uint32_t*)&b3;
        out[i] = o;
    }
}

// ---------------------------------------------------------------------------
// Main fused GEMM (mma.sync bf16 m16n8k16) + online logsumexp.
// Grid (64 row-tiles, 37 slices) = 2368 CTAs = 8 full waves at 2 CTA/SM.
// 256 threads = 8 warps (4m x 2n), 32x64 warp tiles. Slice s owns vocab tiles
// {s, s+37, s+74, ...}.
// ---------------------------------------------------------------------------
__global__ void __launch_bounds__(256, 2)
k_cce(const __nv_bfloat16* __restrict__ ge, const __nv_bfloat16* __restrict__ gc)
{
    extern __shared__ char smem[];
    const uint32_t sb = smem_u32(smem);
    const int tid  = threadIdx.x;
    const int lane = tid & 31;
    const int wid  = tid >> 5;
    const int warp_m = wid & 3;
    const int warp_n = wid >> 2;
    const int row0  = blockIdx.x * BM;
    const int slice = blockIdx.y;
    const int ntiles = (NTILES - slice + NSLICES - 1) / NSLICES;
    const int S = ntiles * KCHUNKS;

    // cp.async per-thread layout: 32 rows x 8 chunks(16B); 4 row-iterations.
    const int ar = tid >> 3;
    const int ac = tid & 7;
    const uint32_t st_off = ar * 128 + ((ac ^ (ar & 7)) << 4);
    const __nv_bfloat16* gA0 = ge + (size_t)(row0 + ar) * DIM + ac * 8;

    // ldmatrix addressing (bytes)
    const int rA0 = warp_m * 32 + (lane & 15);
    const uint32_t aoff0 = rA0 * 128;
    const uint32_t aoff1 = (rA0 + 16) * 128;
    const uint32_t asw   = rA0 & 7;
    const int ahi = lane >> 4;                       // k-half chunk
    const int rB  = ((lane >> 4) << 3) + (lane & 7); // n-row within 16
    uint32_t boff[4];
#pragma unroll
    for (int p = 0; p < 4; p++) boff[p] = (warp_n * 64 + p * 16 + rB) * 128;
    const uint32_t bsw = lane & 7;
    const int bhi = (lane >> 3) & 1;                 // k-half chunk

    // ---- stage loader ----
    auto load_stage = [&](int s, int buf) {
        const int kc   = s & (KCHUNKS - 1);
        const int tix  = slice + (s >> 4) * NSLICES;
        const int col0 = tix * BN;
        const uint32_t as = sb + buf * STAGE_BYTES;
        const uint32_t bs = as + STAGE_A_BYTES;
        const __nv_bfloat16* ga = gA0 + kc * BKE;
#pragma unroll
        for (int i = 0; i < 4; i++)
            cp_async16(as + st_off + i * 4096, ga + (size_t)i * 32 * DIM, 16);
        const int vr0 = col0 + ar;
#pragma unroll
        for (int i = 0; i < 4; i++) {
            int vr = vr0 + i * 32;
            int ok = vr < VOCAB;
            const __nv_bfloat16* gb = gc + (size_t)(ok ? vr : 0) * DIM + kc * BKE + ac * 8;
            cp_async16(bs + st_off + i * 4096, gb, ok ? 16 : 0);  // sz=0 zero-fills
        }
    };

    // ---- pipeline prologue ----
    int s_issue = 0, buf_issue = 0;
#pragma unroll
    for (int i = 0; i < NSTAGES - 1; i++) {
        load_stage(s_issue, buf_issue);
        asm volatile("cp.async.commit_group;" ::: "memory");
        s_issue++;
        buf_issue = (buf_issue == NSTAGES - 1) ? 0 : buf_issue + 1;
    }

    float msta[4], ssta[4];
#pragma unroll
    for (int i = 0; i < 4; i++) { msta[i] = NEG_INF; ssta[i] = 0.0f; }

    int buf_c = 0;
    for (int tt = 0; tt < ntiles; tt++) {
        const int tix  = slice + tt * NSLICES;
        const int col0 = tix * BN;
        const bool boundary = (tix == NTILES - 1);

        float acc[2][8][4];
#pragma unroll
        for (int mt = 0; mt < 2; mt++)
#pragma unroll
            for (int nt = 0; nt < 8; nt++)
#pragma unroll
                for (int k = 0; k < 4; k++) acc[mt][nt][k] = 0.0f;

#pragma unroll 1
        for (int kc = 0; kc < KCHUNKS; kc++) {
            asm volatile("cp.async.wait_group 1;" ::: "memory");
            __syncthreads();
            if (s_issue < S) load_stage(s_issue, buf_issue);
            asm volatile("cp.async.commit_group;" ::: "memory");
            s_issue++;
            buf_issue = (buf_issue == NSTAGES - 1) ? 0 : buf_issue + 1;

            const uint32_t as = sb + buf_c * STAGE_BYTES;
            const uint32_t bs = as + STAGE_A_BYTES;
#pragma unroll
            for (int ks = 0; ks < 4; ks++) {      // 4 x k16 per 64-elt chunk
                uint32_t af[2][4], bf[8][2];
                const uint32_t ach = (uint32_t)(2 * ks + ahi);
                ldsm4(af[0][0], af[0][1], af[0][2], af[0][3],
                      as + aoff0 + ((ach ^ asw) << 4));
                ldsm4(af[1][0], af[1][1], af[1][2], af[1][3],
                      as + aoff1 + ((ach ^ asw) << 4));
                const uint32_t bch = (uint32_t)(2 * ks + bhi);
#pragma unroll
                for (int p = 0; p < 4; p++)
                    ldsm4(bf[2 * p][0], bf[2 * p][1], bf[2 * p + 1][0], bf[2 * p + 1][1],
                          bs + boff[p] + ((bch ^ bsw) << 4));
#pragma unroll
                for (int mt = 0; mt < 2; mt++)
#pragma unroll
                    for (int nt = 0; nt < 8; nt++)
                        mma_bf16(acc[mt][nt], af[mt], bf[nt]);
            }
            buf_c = (buf_c == NSTAGES - 1) ? 0 : buf_c + 1;
        }

        // ---- fused online-logsumexp epilogue on register fragments ----
        const int colt = col0 + warp_n * 64 + 2 * (lane & 3);
#pragma unroll
        for (int mt = 0; mt < 2; mt++) {
#pragma unroll
            for (int h = 0; h < 2; h++) {
                const int rg = mt * 2 + h;
                float tmax = NEG_INF;
#pragma unroll
                for (int nt = 0; nt < 8; nt++)
#pragma unroll
                    for (int j = 0; j < 2; j++) {
                        float v = acc[mt][nt][h * 2 + j];
                        if (boundary && (colt + nt * 8 + j) >= VOCAB) v = NEG_INF;
                        tmax = fmaxf(tmax, v);
                    }
                const float nm = fmaxf(msta[rg], tmax);
                float add = 0.0f;
#pragma unroll
                for (int nt = 0; nt < 8; nt++)
#pragma unroll
                    for (int j = 0; j < 2; j++) {
                        float v = acc[mt][nt][h * 2 + j];
                        if (boundary && (colt + nt * 8 + j) >= VOCAB) v = NEG_INF;
                        add += __expf(v - nm);
                    }
                ssta[rg] = ssta[rg] * __expf(msta[rg] - nm) + add;
                msta[rg] = nm;
            }
        }
    }
    asm volatile("cp.async.wait_group 0;" ::: "memory");

    // ---- merge the 4 lanes of each quad; store per (slice, warp_n) ----
#pragma unroll
    for (int rg = 0; rg < 4; rg++) {
        float m = msta[rg], s = ssta[rg];
#pragma unroll
        for (int off = 1; off <= 2; off <<= 1) {
            float om = __shfl_xor_sync(0xffffffffu, m, off);
            float os = __shfl_xor_sync(0xffffffffu, s, off);
            float nm = fmaxf(m, om);
            s = s * __expf(m - nm) + os * __expf(om - nm);
            m = nm;
        }
        if ((lane & 3) == 0) {
            const int row = row0 + warp_m * 32 + (rg >> 1) * 16 + (rg & 1) * 8 + (lane >> 2);
            const int p = slice * 2 + warp_n;
            g_pm[p * N_TOK + row] = m;
            g_ps[p * N_TOK + row] = s;
        }
    }
}

// ---------------------------------------------------------------------------
// Target dtype sniffing (int64 vs int32)
// ---------------------------------------------------------------------------
__device__ __forceinline__ bool targets_are_i64(const int* t32) {
#pragma unroll
    for (int j = 1; j < 64; j += 2) {
        int w = t32[j];
        if (w != 0 && w != -1) return false;
    }
    return true;
}
__device__ __forceinline__ long long get_target(const void* tp, int row, bool is64) {
    if (is64) return ((const long long*)tp)[row];
    return (long long)((const int*)tp)[row];
}

// ---------------------------------------------------------------------------
// Kernel 2: merge 74 partials -> lse (warp-parallel); exact fp32 target dot
// (float4-vectorized); nll[row].
// ---------------------------------------------------------------------------
__global__ __launch_bounds__(128)
void k_row_nll(const float* __restrict__ e, const float* __restrict__ c,
               const void* __restrict__ targets)
{
    const int row = blockIdx.x;
    __shared__ float sd[128];
    __shared__ bool s_is64;
    if (threadIdx.x == 0) s_is64 = targets_are_i64((const int*)targets);
    __syncthreads();

    long long t = get_target(targets, row, s_is64);
    bool valid = (t != IGNORE);
    int safe = valid ? (int)t : 0;

    // float4-vectorized target dot: 1024 elems = 256 float4, 2 per thread
    const float4* er4 = (const float4*)(e + (size_t)row * DIM);
    const float4* cr4 = (const float4*)(c + (size_t)safe * DIM);
    float4 a0 = er4[threadIdx.x],        b0 = cr4[threadIdx.x];
    float4 a1 = er4[threadIdx.x + 128],  b1 = cr4[threadIdx.x + 128];
    float dot = a0.x * b0.x + a0.y * b0.y + a0.z * b0.z + a0.w * b0.w
              + a1.x * b1.x + a1.y * b1.y + a1.z * b1.z + a1.w * b1.w;
    sd[threadIdx.x] = dot;
    __syncthreads();
    for (int off = 64; off > 0; off >>= 1) {
        if (threadIdx.x < off) sd[threadIdx.x] += sd[threadIdx.x + off];
        __syncthreads();
    }

    // warp 0: parallel merge of 74 slice partials
    if (threadIdx.x < 32) {
        const int lane = threadIdx.x;
        float M = NEG_INF, S = 0.0f;
        for (int p = lane; p < NPART; p += 32) {
            float mj = g_pm[p * N_TOK + row];
            float sj = g_ps[p * N_TOK + row];
            if (mj > NEG_INF) {
                if (mj > M) { S = S * __expf(M - mj) + sj; M = mj; }
                else        { S += sj * __expf(mj - M); }
            }
        }
#pragma unroll
        for (int off = 16; off > 0; off >>= 1) {
            float om = __shfl_xor_sync(0xffffffffu, M, off);
            float os = __shfl_xor_sync(0xffffffffu, S, off);
            float nm = fmaxf(M, om);
            // exp(-inf - -inf) guard: if both -inf, S stays 0
            float e1 = (M > NEG_INF) ? __expf(M - nm) : 0.0f;
            float e2 = (om > NEG_INF) ? __expf(om - nm) : 0.0f;
            S = S * e1 + os * e2;
            M = nm;
        }
        if (lane == 0) {
            float lse = M + logf(S);
            g_nll[row] = valid ? (lse - sd[0]) : 0.0f;
        }
    }
}

// ---------------------------------------------------------------------------
// Kernel 3: deterministic mean over valid rows
// ---------------------------------------------------------------------------
__global__ __launch_bounds__(1024)
void k_reduce(const void* __restrict__ targets, float* __restrict__ out)
{
    __shared__ float ss[1024];
    __shared__ float sc[1024];
    __shared__ bool  s_is64;
    if (threadIdx.x == 0) s_is64 = targets_are_i64((const int*)targets);
    __syncthreads();

    float sum = 0.0f, cnt = 0.0f;
    for (int r = threadIdx.x; r < N_TOK; r += 1024) {
        sum += g_nll[r];
        long long t = get_target(targets, r, s_is64);
        cnt += (t != IGNORE) ? 1.0f : 0.0f;
    }
    ss[threadIdx.x] = sum;
    sc[threadIdx.x] = cnt;
    __syncthreads();
    for (int off = 512; off > 0; off >>= 1) {
        if (threadIdx.x < off) {
            ss[threadIdx.x] += ss[threadIdx.x + off];
            sc[threadIdx.x] += sc[threadIdx.x + off];
        }
        __syncthreads();
    }
    if (threadIdx.x == 0)
        out[0] = ss[0] / fmaxf(sc[0], 1.0f);
}

// ---------------------------------------------------------------------------
// Host launcher
// ---------------------------------------------------------------------------
extern "C" void kernel_launch(void* const* d_in, const int* in_sizes, int n_in,
                              void* d_out, int out_size)
{
    const float* e = (const float*)d_in[0];
    const float* c = (const float*)d_in[1];
    const void*  t = d_in[2];
    float* out = (float*)d_out;

    void* pe = nullptr; void* pc = nullptr;
    cudaGetSymbolAddress(&pe, g_e16);
    cudaGetSymbolAddress(&pc, g_c16);

    // Pre-round inputs to bf16 (RN)
    {
        int n8e = (N_TOK * DIM) / 8;
        int n8c = (VOCAB * DIM) / 8;
        k_cvt<<<(n8e + 255) / 256, 256>>>((const float4*)e, (uint4*)pe, n8e);
        k_cvt<<<(n8c + 255) / 256, 256>>>((const float4*)c, (uint4*)pc, n8c);
    }

    static int smem_set = 0;
    if (!smem_set) {
        cudaFuncSetAttribute(k_cce, cudaFuncAttributeMaxDynamicSharedMemorySize, SMEM_BYTES);
        smem_set = 1;
    }
    dim3 grid(N_TOK / BM, NSLICES);
    k_cce<<<grid, 256, SMEM_BYTES>>>((const __nv_bfloat16*)pe, (const __nv_bfloat16*)pc);

    k_row_nll<<<N_TOK, 128>>>(e, c, t);
    k_reduce<<<1, 1024>>>(t, out);
}